// round 10
// baseline (speedup 1.0000x reference)
#include <cuda_runtime.h>
#include <cstdint>

#define LLF (512*512)
#define NEG_INF_F (-1e10f)

// ---------------- scratch (device globals; no allocation allowed) ----------
__device__ float g_rin [(size_t)65536 * 512];    // tf32-rounded [r1;r2]
__device__ float g_h   [(size_t)65536 * 512];    // MLP hidden (rounded)
__device__ float g_cat [(size_t)65536 * 1024];   // [rm | rc] concat, ld=1024 (rounded)
__device__ float g_rmt [(size_t)65536 * 512];    // r1m^T / r2m^T per-batch
__device__ float g_o   [(size_t)64 * LLF];       // logits (raw fp32)
__device__ float g_o1  [(size_t)64 * LLF];       // row softmax (rounded)
__device__ float g_o2t [(size_t)64 * LLF];       // col softmax transposed (rounded)
__device__ float g_t   [(size_t)65536 * 512];    // compare hidden (rounded)
__device__ float g_w1t [512 * 512];
__device__ float g_w2t [512 * 512];
__device__ float g_wc1t[512 * 1024];
__device__ float g_wc2t[512 * 512];
__device__ float g_mc  [65536];                  // row mask (flat)

// ---------------------------------------------------------------------------
__device__ __forceinline__ unsigned f2tf(float x) {
    unsigned u;
    asm("cvt.rna.tf32.f32 %0, %1;" : "=r"(u) : "f"(x));
    return u;
}
__device__ __forceinline__ float rndtf(float x) { return __uint_as_float(f2tf(x)); }

__device__ __forceinline__ uint32_t smem_u32(const void* p) {
    uint32_t a;
    asm("{ .reg .u64 t; cvta.to.shared.u64 t, %1; cvt.u32.u64 %0, t; }" : "=r"(a) : "l"(p));
    return a;
}
__device__ __forceinline__ void cpa16(uint32_t dst, const float* src) {
    asm volatile("cp.async.cg.shared.global [%0], [%1], 16;\n" :: "r"(dst), "l"(src));
}
__device__ __forceinline__ void cpa_commit() { asm volatile("cp.async.commit_group;\n" ::: "memory"); }
template<int N> __device__ __forceinline__ void cpa_wait() {
    asm volatile("cp.async.wait_group %0;\n" :: "n"(N) : "memory");
}
__device__ __forceinline__ void mma_tf32(float* d, const unsigned* a, const unsigned* b) {
    asm volatile(
        "mma.sync.aligned.m16n8k8.row.col.f32.tf32.tf32.f32 "
        "{%0,%1,%2,%3}, {%4,%5,%6,%7}, {%8,%9}, {%0,%1,%2,%3};"
        : "+f"(d[0]), "+f"(d[1]), "+f"(d[2]), "+f"(d[3])
        : "r"(a[0]), "r"(a[1]), "r"(a[2]), "r"(a[3]), "r"(b[0]), "r"(b[1]));
}
#define LDSM_X4(r, addr) \
    asm volatile("ldmatrix.sync.aligned.m8n8.x4.shared.b16 {%0,%1,%2,%3}, [%4];" \
        : "=r"((r)[0]), "=r"((r)[1]), "=r"((r)[2]), "=r"((r)[3]) : "r"(addr))

// ---------------------------------------------------------------------------
// mma.sync tf32 GEMM.  CTA tile M=128 x N=256, Kc=32, 3-stage cp.async ring.
// Warp tile 64x64 (8 warps, 2M x 4N).  Fragments via ldmatrix.x4, padded rows.
// C = epi(A @ B^T): A row-major [M,K] (lda), B row-major [N,K] (ldb).
// Grid: x = m_tiles*2 + n_tile; y = batch.
// All A/B inputs must be pre-rounded to tf32 in gmem.
// ---------------------------------------------------------------------------
#define ROWP 36                           // floats per padded row (144 B)
#define A_BYTES (128 * ROWP * 4)          // 18432
#define B_BYTES (256 * ROWP * 4)          // 36864
#define STAGE_BYTES (A_BYTES + B_BYTES)   // 55296
#define SMEM_TOT (3 * STAGE_BYTES)        // 165888

template<int HAS_BIAS, int LRELU, int ROWMASK, int OMASK, int ROUND>
__global__ __launch_bounds__(256)
void tgemm(const float* __restrict__ A_, const float* __restrict__ B_, float* __restrict__ C_,
           int lda, int ldb, int ldc, int K,
           long sA, long sB, long sC,
           const float* __restrict__ bias, const float* __restrict__ maskc,
           const int* __restrict__ m1, const int* __restrict__ m2)
{
    extern __shared__ __align__(1024) char smem[];
    const int t = threadIdx.x, warp = t >> 5, lane = t & 31;
    const int bat = blockIdx.y;
    const int n0 = (blockIdx.x & 1) * 256;
    const int m0 = (blockIdx.x >> 1) * 128;
    const float* A = A_ + (size_t)bat * sA;
    const float* B = B_ + (size_t)bat * sB;
    float*       C = C_ + (size_t)bat * sC;

    const uint32_t sm = smem_u32(smem);
    const int wm = (warp & 1) * 64;
    const int wn = (warp >> 1) * 64;

    // per-lane ldmatrix base addresses (within stage 0)
    const int arow = ((lane >> 3) & 1) * 8 + (lane & 7);
    const int akh  = (lane >> 4);               // k half (0/1 -> +16B)
    const uint32_t aBase = sm + (uint32_t)(wm + arow) * (ROWP * 4) + akh * 16;
    const int brow = (lane >> 4) * 8 + (lane & 7);
    const int bkh  = ((lane >> 3) & 1);
    const uint32_t bBase = sm + A_BYTES + (uint32_t)(wn + brow) * (ROWP * 4) + bkh * 16;

    float acc[4][8][4];
    #pragma unroll
    for (int i = 0; i < 4; i++)
        #pragma unroll
        for (int j = 0; j < 8; j++)
            #pragma unroll
            for (int q = 0; q < 4; q++) acc[i][j][q] = 0.f;

    const int S = K >> 5;

    auto load_stage = [&](int s) {
        const uint32_t so = (uint32_t)(s % 3) * STAGE_BYTES;
        const int k0 = s << 5;
        #pragma unroll
        for (int i = 0; i < 4; i++) {                 // A: 128 rows x 8 chunks
            int q = t + 256 * i;
            int row = q >> 3, kq = q & 7;
            cpa16(sm + so + (uint32_t)row * (ROWP * 4) + kq * 16,
                  A + (size_t)(m0 + row) * lda + k0 + kq * 4);
        }
        #pragma unroll
        for (int i = 0; i < 8; i++) {                 // B: 256 rows x 8 chunks
            int q = t + 256 * i;
            int row = q >> 3, kq = q & 7;
            cpa16(sm + so + A_BYTES + (uint32_t)row * (ROWP * 4) + kq * 16,
                  B + (size_t)(n0 + row) * ldb + k0 + kq * 4);
        }
        cpa_commit();
    };

    load_stage(0); load_stage(1); load_stage(2);

    for (int s = 0; s < S; s++) {
        const int rem = S - 1 - s;
        if (rem >= 2)      cpa_wait<2>();
        else if (rem == 1) cpa_wait<1>();
        else               cpa_wait<0>();
        __syncthreads();

        const uint32_t so = (uint32_t)(s % 3) * STAGE_BYTES;
        #pragma unroll
        for (int ks = 0; ks < 4; ks++) {
            const uint32_t ko = ks * 32;              // 8 floats = 32 B
            unsigned af[4][4], bf[4][4];
            #pragma unroll
            for (int mt = 0; mt < 4; mt++)
                LDSM_X4(af[mt], aBase + so + mt * (16 * ROWP * 4) + ko);
            #pragma unroll
            for (int np = 0; np < 4; np++)
                LDSM_X4(bf[np], bBase + so + np * (16 * ROWP * 4) + ko);
            #pragma unroll
            for (int mt = 0; mt < 4; mt++)
                #pragma unroll
                for (int nt = 0; nt < 8; nt++)
                    mma_tf32(acc[mt][nt], af[mt], &bf[nt >> 1][(nt & 1) * 2]);
        }
        __syncthreads();
        if (s + 3 < S) load_stage(s + 3);
    }

    // epilogue
    const int r  = lane >> 2, cq = lane & 3;
    #pragma unroll
    for (int mt = 0; mt < 4; mt++) {
        const int gr0 = m0 + wm + mt * 16 + r;
        const int gr1 = gr0 + 8;
        float mv0 = 1.f, mv1 = 1.f;
        int mi0 = 1, mi1 = 1;
        if (ROWMASK) { mv0 = maskc[gr0]; mv1 = maskc[gr1]; }
        if (OMASK)   { mi0 = m1[bat * 512 + gr0]; mi1 = m1[bat * 512 + gr1]; }
        #pragma unroll
        for (int nt = 0; nt < 8; nt++) {
            const int gc = n0 + wn + nt * 8 + cq * 2;
            float c0 = acc[mt][nt][0], c1 = acc[mt][nt][1];
            float c2 = acc[mt][nt][2], c3 = acc[mt][nt][3];
            if (HAS_BIAS) {
                const float bb0 = bias[gc], bb1 = bias[gc + 1];
                c0 += bb0; c1 += bb1; c2 += bb0; c3 += bb1;
            }
            if (LRELU) {
                c0 = (c0 >= 0.f) ? c0 : 0.01f * c0;
                c1 = (c1 >= 0.f) ? c1 : 0.01f * c1;
                c2 = (c2 >= 0.f) ? c2 : 0.01f * c2;
                c3 = (c3 >= 0.f) ? c3 : 0.01f * c3;
            }
            if (ROWMASK) { c0 *= mv0; c1 *= mv0; c2 *= mv1; c3 *= mv1; }
            if (OMASK) {
                const int mj0 = m2[bat * 512 + gc];
                const int mj1 = m2[bat * 512 + gc + 1];
                c0 = (mi0 && mj0) ? c0 : NEG_INF_F;
                c1 = (mi0 && mj1) ? c1 : NEG_INF_F;
                c2 = (mi1 && mj0) ? c2 : NEG_INF_F;
                c3 = (mi1 && mj1) ? c3 : NEG_INF_F;
            }
            if (ROUND) { c0 = rndtf(c0); c1 = rndtf(c1); c2 = rndtf(c2); c3 = rndtf(c3); }
            *(float2*)(C + (size_t)gr0 * ldc + gc) = make_float2(c0, c1);
            *(float2*)(C + (size_t)gr1 * ldc + gc) = make_float2(c2, c3);
        }
    }
}

// ---------------------------------------------------------------------------
// Prep kernels
// ---------------------------------------------------------------------------
__global__ void prep_round_inputs(const float* __restrict__ r1, const float* __restrict__ r2,
                                  float* __restrict__ rin)
{
    size_t i = (size_t)blockIdx.x * 256 + threadIdx.x;
    const size_t HALF = (size_t)32768 * 512;
    if (i < HALF)            rin[i] = rndtf(r1[i]);
    else if (i < 2 * HALF)   rin[i] = rndtf(r2[i - HALF]);
}
__global__ void prep_mask(const int* __restrict__ m1, const int* __restrict__ m2,
                          float* __restrict__ mc)
{
    int i = blockIdx.x * 256 + threadIdx.x;
    if (i < 65536) mc[i] = (i < 32768 ? m1[i] : m2[i - 32768]) ? 1.f : 0.f;
}
// out[c*R + r] = rna(in[r*Ncol + c])
__global__ void transposeW(const float* __restrict__ in, float* __restrict__ out, int R, int Ncol)
{
    int i = blockIdx.x * 256 + threadIdx.x;
    if (i < R * Ncol) {
        int r = i / Ncol, c = i - r * Ncol;
        out[(size_t)c * R + r] = rndtf(in[i]);
    }
}
// rmT[p][b][d][j] = cat[(p*32768 + b*512 + j)*1024 + d]
__global__ __launch_bounds__(256) void transpose_rm(const float* __restrict__ cat,
                                                    float* __restrict__ rmt)
{
    __shared__ float tile[32][33];
    const int tx = threadIdx.x, ty = threadIdx.y;       // block (32, 8)
    const int j0 = blockIdx.x * 32, d0 = blockIdx.y * 32;
    const size_t P = (size_t)blockIdx.z * 512;
    #pragma unroll
    for (int r = 0; r < 4; r++) {
        int j = ty + 8 * r;
        tile[j][tx] = cat[(P + j0 + j) * 1024 + d0 + tx];
    }
    __syncthreads();
    #pragma unroll
    for (int r = 0; r < 4; r++) {
        int d = ty + 8 * r;
        rmt[(P + d0 + d) * 512 + j0 + tx] = tile[tx][d];
    }
}

// ---------------------------------------------------------------------------
// Softmaxes (outputs tf32-rounded: they feed GEMMs)
// ---------------------------------------------------------------------------
__global__ __launch_bounds__(256) void softmax_row(
    const float* __restrict__ o, float* __restrict__ o1,
    const int* __restrict__ m1, const int* __restrict__ m2)
{
    const int r = blockIdx.x;
    const int b = r >> 9;
    const int t = threadIdx.x;
    const float* row = o + (size_t)r * 512;

    float x0 = row[t];
    float x1 = row[t + 256];

    __shared__ float smx[8];
    __shared__ float ssm[8];

    float mx = fmaxf(x0, x1);
    #pragma unroll
    for (int s = 16; s; s >>= 1) mx = fmaxf(mx, __shfl_xor_sync(0xffffffffu, mx, s));
    if ((t & 31) == 0) smx[t >> 5] = mx;
    __syncthreads();
    float bm = smx[0];
    #pragma unroll
    for (int w = 1; w < 8; w++) bm = fmaxf(bm, smx[w]);

    float e0 = __expf(x0 - bm);
    float e1 = __expf(x1 - bm);
    float s = e0 + e1;
    #pragma unroll
    for (int sh = 16; sh; sh >>= 1) s += __shfl_xor_sync(0xffffffffu, s, sh);
    if ((t & 31) == 0) ssm[t >> 5] = s;
    __syncthreads();
    float tot = 0.f;
    #pragma unroll
    for (int w = 0; w < 8; w++) tot += ssm[w];

    const float inv = 1.f / tot;
    const float mrow = m1[r] ? 1.f : 0.f;
    o1[(size_t)r * 512 + t]       = rndtf(e0 * inv * mrow * (m2[b * 512 + t]       ? 1.f : 0.f));
    o1[(size_t)r * 512 + t + 256] = rndtf(e1 * inv * mrow * (m2[b * 512 + t + 256] ? 1.f : 0.f));
}

__global__ __launch_bounds__(128) void softmax_col(
    const float* __restrict__ o, float* __restrict__ o2t,
    const int* __restrict__ m1, const int* __restrict__ m2)
{
    const int b = blockIdx.y;
    const int j = blockIdx.x * 128 + threadIdx.x;

    __shared__ float m1s[512];
    for (int i = threadIdx.x; i < 512; i += 128)
        m1s[i] = m1[b * 512 + i] ? 1.f : 0.f;
    __syncthreads();

    const float* ob = o + (size_t)b * LLF;
    float mx = -3.4e38f, sum = 0.f;
    for (int i = 0; i < 512; i++) {
        float v = ob[(size_t)i * 512 + j];
        float nm = fmaxf(mx, v);
        sum = sum * __expf(mx - nm) + __expf(v - nm);
        mx = nm;
    }
    const float inv = 1.f / sum;
    const float mjv = m2[b * 512 + j] ? 1.f : 0.f;

    float* orow = o2t + (size_t)b * LLF + (size_t)j * 512;
    for (int i = 0; i < 512; i++) {
        float v = ob[(size_t)i * 512 + j];
        orow[i] = rndtf(__expf(v - mx) * inv * mjv * m1s[i]);
    }
}

// ---------------------------------------------------------------------------
extern "C" void kernel_launch(void* const* d_in, const int* in_sizes, int n_in,
                              void* d_out, int out_size)
{
    (void)in_sizes; (void)n_in; (void)out_size;
    const float* r1    = (const float*)d_in[0];
    const float* r2    = (const float*)d_in[1];
    const int*   mask1 = (const int*)  d_in[2];
    const int*   mask2 = (const int*)  d_in[3];
    const float* W1    = (const float*)d_in[4];
    const float* b1    = (const float*)d_in[5];
    const float* W2    = (const float*)d_in[6];
    const float* b2    = (const float*)d_in[7];
    const float* Wc1   = (const float*)d_in[8];
    const float* bc1   = (const float*)d_in[9];
    const float* Wc2   = (const float*)d_in[10];
    const float* bc2   = (const float*)d_in[11];
    float* out = (float*)d_out;

    float *rin, *h, *cat, *rmt, *o, *o1, *o2t, *tb;
    float *w1t, *w2t, *wc1t, *wc2t, *mc;
    cudaGetSymbolAddress((void**)&rin,  g_rin);
    cudaGetSymbolAddress((void**)&h,    g_h);
    cudaGetSymbolAddress((void**)&cat,  g_cat);
    cudaGetSymbolAddress((void**)&rmt,  g_rmt);
    cudaGetSymbolAddress((void**)&o,    g_o);
    cudaGetSymbolAddress((void**)&o1,   g_o1);
    cudaGetSymbolAddress((void**)&o2t,  g_o2t);
    cudaGetSymbolAddress((void**)&tb,   g_t);
    cudaGetSymbolAddress((void**)&w1t,  g_w1t);
    cudaGetSymbolAddress((void**)&w2t,  g_w2t);
    cudaGetSymbolAddress((void**)&wc1t, g_wc1t);
    cudaGetSymbolAddress((void**)&wc2t, g_wc2t);
    cudaGetSymbolAddress((void**)&mc,   g_mc);

    cudaFuncSetAttribute((const void*)tgemm<1,1,0,0,1>, cudaFuncAttributeMaxDynamicSharedMemorySize, SMEM_TOT);
    cudaFuncSetAttribute((const void*)tgemm<1,1,1,0,1>, cudaFuncAttributeMaxDynamicSharedMemorySize, SMEM_TOT);
    cudaFuncSetAttribute((const void*)tgemm<0,0,0,1,0>, cudaFuncAttributeMaxDynamicSharedMemorySize, SMEM_TOT);
    cudaFuncSetAttribute((const void*)tgemm<0,0,0,0,1>, cudaFuncAttributeMaxDynamicSharedMemorySize, SMEM_TOT);
    cudaFuncSetAttribute((const void*)tgemm<1,1,1,0,0>, cudaFuncAttributeMaxDynamicSharedMemorySize, SMEM_TOT);

    const size_t HOFF_CAT = (size_t)32768 * 1024;
    const size_t HOFF_T   = (size_t)32768 * 512;

    // prep
    prep_round_inputs<<<131072, 256>>>(r1, r2, rin);
    prep_mask<<<256, 256>>>(mask1, mask2, mc);
    transposeW<<<1024, 256>>>(W1,  w1t,  512, 512);
    transposeW<<<1024, 256>>>(W2,  w2t,  512, 512);
    transposeW<<<2048, 256>>>(Wc1, wc1t, 1024, 512);
    transposeW<<<1024, 256>>>(Wc2, wc2t, 512, 512);

    // flat grids: (65536/128 m-tiles)*(512/256 n-tiles) = 1024
    // batched grids: (512/128)*(512/256) = 8 tiles x 64 batches
    dim3 gflat(1024, 1), gbat(8, 64);

    // 1. H = lrelu(Rin @ W1^T' + b1), rounded
    tgemm<1,1,0,0,1><<<gflat, 256, SMEM_TOT>>>(rin, w1t, h, 512, 512, 512, 512,
        0, 0, 0, b1, nullptr, nullptr, nullptr);
    // 2. RM = lrelu(H @ W2 + b2) * mask, rounded -> cat cols 0..511
    tgemm<1,1,1,0,1><<<gflat, 256, SMEM_TOT>>>(h, w2t, cat, 512, 512, 1024, 512,
        0, 0, 0, b2, mc, nullptr, nullptr);
    // transposed rm copies for the context GEMMs
    transpose_rm<<<dim3(16,16,128), dim3(32,8)>>>(cat, rmt);
    // 3. logits: o = r1m @ r2m^T + mask_inf
    tgemm<0,0,0,1,0><<<gbat, 256, SMEM_TOT>>>(cat, cat + HOFF_CAT, o,
        1024, 1024, 512, 512,
        (long)512*1024, (long)512*1024, (long)LLF, nullptr, nullptr, mask1, mask2);
    // softmaxes
    softmax_row<<<32768, 256>>>(o, o1, mask1, mask2);
    softmax_col<<<dim3(4,64), 128>>>(o, o2t, mask1, mask2);
    // 4. r1_c = o1 @ r2m -> cat cols 512..1023 (r1 side)
    tgemm<0,0,0,0,1><<<gbat, 256, SMEM_TOT>>>(o1, rmt + HOFF_T, cat + 512,
        512, 512, 1024, 512,
        (long)LLF, (long)LLF, (long)512*1024, nullptr, nullptr, nullptr, nullptr);
    // 5. r2_c = o2^T @ r1m -> cat cols 512..1023 (r2 side)
    tgemm<0,0,0,0,1><<<gbat, 256, SMEM_TOT>>>(o2t, rmt, cat + HOFF_CAT + 512,
        512, 512, 1024, 512,
        (long)LLF, (long)LLF, (long)512*1024, nullptr, nullptr, nullptr, nullptr);
    // 6. T = lrelu([RM|RC] @ Wc1 + bc1), rounded (K=1024)
    tgemm<1,1,0,0,1><<<gflat, 256, SMEM_TOT>>>(cat, wc1t, tb, 1024, 1024, 512, 1024,
        0, 0, 0, bc1, nullptr, nullptr, nullptr);
    // 7. OUT = lrelu(T @ Wc2 + bc2) * mask (no rounding)
    tgemm<1,1,1,0,0><<<gflat, 256, SMEM_TOT>>>(tb, wc2t, out, 512, 512, 512, 512,
        0, 0, 0, bc2, mc, nullptr, nullptr);
}